// round 2
// baseline (speedup 1.0000x reference)
#include <cuda_runtime.h>

#define BB 4096
#define SS 128
#define EH 128
#define DH 256
#define NDEC 10

typedef unsigned long long u64;

// context scratch (encoder -> decoder)
__device__ float g_ctx[BB * EH];

__device__ __forceinline__ u64 ffma2(u64 a, u64 b, u64 c) {
    u64 d;
    asm("fma.rn.f32x2 %0, %1, %2, %3;" : "=l"(d) : "l"(a), "l"(b), "l"(c));
    return d;
}
__device__ __forceinline__ float f2sum(u64 a) {
    float lo = __int_as_float((unsigned)(a & 0xffffffffULL));
    float hi = __int_as_float((unsigned)(a >> 32));
    return lo + hi;
}
__device__ __forceinline__ float sigf(float v) {
    return __fdividef(1.f, 1.f + __expf(-v));
}
__device__ __forceinline__ float tanhfast(float v) {
    float e = __expf(2.f * v);
    return 1.f - __fdividef(2.f, e + 1.f);
}

// ---------------------------------------------------------------------------
// Encoder: persistent GRU. 128 blocks x 256 threads, 32 batch rows per block.
// Whh resident in SMEM (stride 132 -> conflict-free 16B LDS for 2-col threads).
// Thread owns 8 rows x 2 channels x 3 gates (cols cg, cg+64 and +128/+256 offs).
// ---------------------------------------------------------------------------
#define E_WSTR 132
#define E_SMEM_FLOATS (384 * E_WSTR + 32 * 128 + 384 * 5 + 384 + 384 + 160)
#define E_SMEM_BYTES (E_SMEM_FLOATS * 4)

__global__ void __launch_bounds__(256, 1)
enc_kernel(const float* __restrict__ x, const float* __restrict__ Wih,
           const float* __restrict__ Whh, const float* __restrict__ bih,
           const float* __restrict__ bhh)
{
    extern __shared__ float sm[];
    float* Whh_s = sm;                      // 384*132
    float* h_s   = Whh_s + 384 * E_WSTR;    // 32*128
    float* Wih_s = h_s + 32 * 128;          // 384*5
    float* bih_s = Wih_s + 384 * 5;         // 384
    float* bhh_s = bih_s + 384;             // 384
    float* x_s   = bhh_s + 384;             // 32*5

    const int tid = threadIdx.x;
    const int b0 = blockIdx.x * 32;

    for (int u = tid; u < 384 * 32; u += 256) {
        int c = u >> 5, q = u & 31;
        *(float4*)(Whh_s + c * E_WSTR + q * 4) =
            *(const float4*)(Whh + c * 128 + q * 4);
    }
    for (int u = tid; u < 384 * 5; u += 256) Wih_s[u] = Wih[u];
    for (int u = tid; u < 384; u += 256) {   // FIX: was `if (tid < 384)` with 256 threads
        bih_s[u] = bih[u];
        bhh_s[u] = bhh[u];
    }
    for (int u = tid; u < 32 * 128; u += 256) h_s[u] = 0.f;
    if (tid < 160)
        x_s[tid] = x[(long)(b0 + tid / 5) * (SS * 5) + (tid % 5)];
    __syncthreads();

    const int rg = tid >> 6;      // 0..3 (warp-uniform -> h_s reads broadcast)
    const int cg = tid & 63;      // 0..63
    const int r0 = rg * 8;
    int col[6];
#pragma unroll
    for (int m = 0; m < 6; m++) col[m] = cg + m * 64;

    const float* wp[6];
#pragma unroll
    for (int m = 0; m < 6; m++) wp[m] = Whh_s + col[m] * E_WSTR;

    for (int t = 0; t < SS; ++t) {
        u64 acc[8][6];
#pragma unroll
        for (int i = 0; i < 8; i++)
#pragma unroll
            for (int m = 0; m < 6; m++) acc[i][m] = 0ULL;

#pragma unroll 2
        for (int kq = 0; kq < 32; ++kq) {
            ulonglong2 w2[6];
#pragma unroll
            for (int m = 0; m < 6; m++)
                w2[m] = *(const ulonglong2*)(wp[m] + kq * 4);
#pragma unroll
            for (int i = 0; i < 8; i++) {
                ulonglong2 hv = *(const ulonglong2*)(h_s + (r0 + i) * 128 + kq * 4);
#pragma unroll
                for (int m = 0; m < 6; m++) {
                    acc[i][m] = ffma2(hv.x, w2[m].x, acc[i][m]);
                    acc[i][m] = ffma2(hv.y, w2[m].y, acc[i][m]);
                }
            }
        }

        float hnew[8][2];
#pragma unroll
        for (int i = 0; i < 8; i++) {
            float xv[5];
#pragma unroll
            for (int j = 0; j < 5; j++) xv[j] = x_s[(r0 + i) * 5 + j];
#pragma unroll
            for (int cc = 0; cc < 2; ++cc) {
                int cr = col[cc], cz = col[cc + 2], cn = col[cc + 4];
                float gir = bih_s[cr], giz = bih_s[cz], gin = bih_s[cn];
#pragma unroll
                for (int j = 0; j < 5; j++) {
                    gir += xv[j] * Wih_s[cr * 5 + j];
                    giz += xv[j] * Wih_s[cz * 5 + j];
                    gin += xv[j] * Wih_s[cn * 5 + j];
                }
                float ghr = f2sum(acc[i][cc])     + bhh_s[cr];
                float ghz = f2sum(acc[i][cc + 2]) + bhh_s[cz];
                float ghn = f2sum(acc[i][cc + 4]) + bhh_s[cn];
                float rr = sigf(gir + ghr);
                float zz = sigf(giz + ghz);
                float nn = tanhfast(gin + rr * ghn);
                float hold = h_s[(r0 + i) * 128 + col[cc]];
                hnew[i][cc] = (1.f - zz) * nn + zz * hold;
            }
        }
        __syncthreads();   // all reads of h_s / x_s complete
#pragma unroll
        for (int i = 0; i < 8; i++) {
            h_s[(r0 + i) * 128 + col[0]] = hnew[i][0];
            h_s[(r0 + i) * 128 + col[1]] = hnew[i][1];
        }
        if (t + 1 < SS && tid < 160)
            x_s[tid] = x[(long)(b0 + tid / 5) * (SS * 5) + (t + 1) * 5 + (tid % 5)];
        __syncthreads();   // writes visible
    }

    for (int u = tid; u < 32 * 32; u += 256) {
        int r = u >> 5, q = u & 31;
        *(float4*)(g_ctx + (long)(b0 + r) * 128 + q * 4) =
            *(float4*)(h_s + r * 128 + q * 4);
    }
}

// ---------------------------------------------------------------------------
// Decoder: persistent GRU. 256 blocks x 256 threads, 16 batch rows per block.
// gi_ctx (= bih + ctx @ Wih[:, :128]^T) computed once, held in SMEM.
// dec_Whh streamed from L2 in double-buffered k=16 chunks (stride 20,
// conflict-free & 16B-aligned).
// ---------------------------------------------------------------------------
#define D_WSTR 20
#define D_SMEM_FLOATS (2 * 768 * D_WSTR + 16 * 768 + 16 * 256 + 768 + 768 + 1024 + 4)
#define D_SMEM_BYTES (D_SMEM_FLOATS * 4)

__global__ void __launch_bounds__(256, 1)
dec_kernel(const float* __restrict__ y, const float* __restrict__ Wih,
           const float* __restrict__ Whh, const float* __restrict__ bih,
           const float* __restrict__ bhh, const float* __restrict__ linW,
           const float* __restrict__ linb, float* __restrict__ out)
{
    extern __shared__ float sm[];
    float* Wc    = sm;                       // 2 * 768*20 (ping-pong)
    float* gi_s  = Wc + 2 * 768 * D_WSTR;    // 16*768
    float* h2_s  = gi_s + 16 * 768;          // 16*256
    float* wy_s  = h2_s + 16 * 256;          // 768
    float* bhh_s = wy_s + 768;               // 768
    float* lw_s  = bhh_s + 768;              // 1024
    float* lb_s  = lw_s + 1024;              // 4

    const int tid = threadIdx.x;
    const int b0 = blockIdx.x * 16;
    const int rg = tid >> 7, cg = tid & 127;
    const int r0 = rg * 8;
    int col[6];
#pragma unroll
    for (int m = 0; m < 6; m++) col[m] = cg + m * 128;

    for (int u = tid; u < 768; u += 256) {
        wy_s[u]  = Wih[(long)u * 129 + 128];
        bhh_s[u] = bhh[u];
    }
    for (int u = tid; u < 1024; u += 256) lw_s[u] = linW[u];
    if (tid < 4) lb_s[tid] = linb[tid];

    // stage context into h2_s region (rows 16 x 128, stride 256)
    for (int u = tid; u < 16 * 32; u += 256) {
        int r = u >> 5, q = u & 31;
        *(float4*)(h2_s + r * 256 + q * 4) =
            *(const float4*)(g_ctx + (long)(b0 + r) * 128 + q * 4);
    }
    __syncthreads();

    // gi_ctx = bih + ctx @ Wih[:, :128]^T  (once; reused for all 10 steps)
    {
        u64 acc[8][6];
#pragma unroll
        for (int i = 0; i < 8; i++)
#pragma unroll
            for (int m = 0; m < 6; m++) acc[i][m] = 0ULL;
        for (int kc = 0; kc < 8; ++kc) {
            __syncthreads();
            for (int u = tid; u < 768 * 16; u += 256) {
                int c = u >> 4, q = u & 15;
                Wc[c * D_WSTR + q] = Wih[(long)c * 129 + kc * 16 + q];
            }
            __syncthreads();
#pragma unroll
            for (int kq = 0; kq < 4; ++kq) {
                ulonglong2 w2[6];
#pragma unroll
                for (int m = 0; m < 6; m++)
                    w2[m] = *(const ulonglong2*)(Wc + col[m] * D_WSTR + kq * 4);
#pragma unroll
                for (int i = 0; i < 8; i++) {
                    ulonglong2 hv =
                        *(const ulonglong2*)(h2_s + (r0 + i) * 256 + kc * 16 + kq * 4);
#pragma unroll
                    for (int m = 0; m < 6; m++) {
                        acc[i][m] = ffma2(hv.x, w2[m].x, acc[i][m]);
                        acc[i][m] = ffma2(hv.y, w2[m].y, acc[i][m]);
                    }
                }
            }
        }
        __syncthreads();
#pragma unroll
        for (int i = 0; i < 8; i++)
#pragma unroll
            for (int m = 0; m < 6; m++)
                gi_s[(r0 + i) * 768 + col[m]] = f2sum(acc[i][m]) + bih[col[m]];
    }
    __syncthreads();
    for (int u = tid; u < 16 * 256; u += 256) h2_s[u] = 1.f;  // h_dec0 = ones
    __syncthreads();

    for (int t = 0; t < NDEC; ++t) {
        float yv[8];
#pragma unroll
        for (int i = 0; i < 8; i++)
            yv[i] = y[(long)(b0 + r0 + i) * SS + t];

        u64 acc[8][6];
#pragma unroll
        for (int i = 0; i < 8; i++)
#pragma unroll
            for (int m = 0; m < 6; m++) acc[i][m] = 0ULL;

        // preload chunk 0
        for (int u = tid; u < 768 * 4; u += 256) {
            int c = u >> 2, q = u & 3;
            *(float4*)(Wc + c * D_WSTR + q * 4) =
                *(const float4*)(Whh + (long)c * 256 + q * 4);
        }
        __syncthreads();

        for (int kc = 0; kc < 16; ++kc) {
            if (kc + 1 < 16) {
                float* dst = Wc + ((kc + 1) & 1) * (768 * D_WSTR);
                const float* src = Whh + (kc + 1) * 16;
                for (int u = tid; u < 768 * 4; u += 256) {
                    int c = u >> 2, q = u & 3;
                    *(float4*)(dst + c * D_WSTR + q * 4) =
                        *(const float4*)(src + (long)c * 256 + q * 4);
                }
            }
            const float* wb = Wc + (kc & 1) * (768 * D_WSTR);
#pragma unroll
            for (int kq = 0; kq < 4; ++kq) {
                ulonglong2 w2[6];
#pragma unroll
                for (int m = 0; m < 6; m++)
                    w2[m] = *(const ulonglong2*)(wb + col[m] * D_WSTR + kq * 4);
#pragma unroll
                for (int i = 0; i < 8; i++) {
                    ulonglong2 hv =
                        *(const ulonglong2*)(h2_s + (r0 + i) * 256 + kc * 16 + kq * 4);
#pragma unroll
                    for (int m = 0; m < 6; m++) {
                        acc[i][m] = ffma2(hv.x, w2[m].x, acc[i][m]);
                        acc[i][m] = ffma2(hv.y, w2[m].y, acc[i][m]);
                    }
                }
            }
            __syncthreads();
        }

        float hnew[8][2];
#pragma unroll
        for (int i = 0; i < 8; i++) {
#pragma unroll
            for (int cc = 0; cc < 2; ++cc) {
                int cr = col[cc], cz = col[cc + 2], cn = col[cc + 4];
                float gir = gi_s[(r0 + i) * 768 + cr] + yv[i] * wy_s[cr];
                float giz = gi_s[(r0 + i) * 768 + cz] + yv[i] * wy_s[cz];
                float gin = gi_s[(r0 + i) * 768 + cn] + yv[i] * wy_s[cn];
                float ghr = f2sum(acc[i][cc])     + bhh_s[cr];
                float ghz = f2sum(acc[i][cc + 2]) + bhh_s[cz];
                float ghn = f2sum(acc[i][cc + 4]) + bhh_s[cn];
                float rr = sigf(gir + ghr);
                float zz = sigf(giz + ghz);
                float nn = tanhfast(gin + rr * ghn);
                float hold = h2_s[(r0 + i) * 256 + col[cc]];
                hnew[i][cc] = (1.f - zz) * nn + zz * hold;
            }
        }
        __syncthreads();
#pragma unroll
        for (int i = 0; i < 8; i++) {
            h2_s[(r0 + i) * 256 + col[0]] = hnew[i][0];
            h2_s[(r0 + i) * 256 + col[1]] = hnew[i][1];
        }
        __syncthreads();

        // out[b, t, :] = h2_new @ lin_W^T + lin_b
        if (tid < 64) {
            int r = tid >> 2, o = tid & 3;
            float s = lb_s[o];
#pragma unroll 4
            for (int q = 0; q < 64; ++q) {
                float4 hv = *(float4*)(h2_s + r * 256 + q * 4);
                float4 wv = *(float4*)(lw_s + o * 256 + q * 4);
                s += hv.x * wv.x + hv.y * wv.y + hv.z * wv.z + hv.w * wv.w;
            }
            out[(long)(b0 + r) * (SS * 4) + t * 4 + o] = s;
        }
    }
}

// ---------------------------------------------------------------------------
__global__ void fill_ones_kernel(float4* out, int n4) {
    int i = blockIdx.x * blockDim.x + threadIdx.x;
    if (i < n4) out[i] = make_float4(1.f, 1.f, 1.f, 1.f);
}

extern "C" void kernel_launch(void* const* d_in, const int* in_sizes, int n_in,
                              void* d_out, int out_size) {
    const float* x    = (const float*)d_in[0];
    const float* y    = (const float*)d_in[1];
    const float* eWih = (const float*)d_in[2];
    const float* eWhh = (const float*)d_in[3];
    const float* ebih = (const float*)d_in[4];
    const float* ebhh = (const float*)d_in[5];
    const float* dWih = (const float*)d_in[6];
    const float* dWhh = (const float*)d_in[7];
    const float* dbih = (const float*)d_in[8];
    const float* dbhh = (const float*)d_in[9];
    const float* lW   = (const float*)d_in[10];
    const float* lb   = (const float*)d_in[11];
    float* out = (float*)d_out;

    cudaFuncSetAttribute(enc_kernel, cudaFuncAttributeMaxDynamicSharedMemorySize,
                         E_SMEM_BYTES);
    cudaFuncSetAttribute(dec_kernel, cudaFuncAttributeMaxDynamicSharedMemorySize,
                         D_SMEM_BYTES);

    int n4 = out_size / 4;
    fill_ones_kernel<<<(n4 + 255) / 256, 256>>>((float4*)out, n4);
    enc_kernel<<<BB / 32, 256, E_SMEM_BYTES>>>(x, eWih, eWhh, ebih, ebhh);
    dec_kernel<<<BB / 16, 256, D_SMEM_BYTES>>>(y, dWih, dWhh, dbih, dbhh, lW, lb, out);
}